// round 13
// baseline (speedup 1.0000x reference)
#include <cuda_runtime.h>
#include <cuda_bf16.h>
#include <math.h>

// ---------------- scratch (device globals: allocation-free rule) -------------
__device__ float g_feat[512 * 8192];   // chain output features
__device__ float g_h1[512 * 4096];     // MLP hidden 1
__device__ float g_h2[512 * 4096];     // MLP hidden 2

// pre-split fragment-major bf16 buffers (hi / lo residual)
__device__ __nv_bfloat16 g_fah[512 * 8192];
__device__ __nv_bfloat16 g_fal[512 * 8192];
__device__ __nv_bfloat16 g_h1ah[512 * 4096];
__device__ __nv_bfloat16 g_h1al[512 * 4096];
__device__ __nv_bfloat16 g_w1h[4096 * 8192];
__device__ __nv_bfloat16 g_w1l[4096 * 8192];
__device__ __nv_bfloat16 g_w2h[4096 * 4096];
__device__ __nv_bfloat16 g_w2l[4096 * 4096];

__device__ __forceinline__ float mishf(float x) {
    float sp = (x > 20.f) ? x : log1pf(expf(x));
    return x * tanhf(sp);
}

__device__ __forceinline__ void mma_m16n8k16(float c[4], const unsigned a[4], const unsigned b[2]) {
    asm volatile(
        "mma.sync.aligned.m16n8k16.row.col.f32.bf16.bf16.f32 "
        "{%0,%1,%2,%3}, {%4,%5,%6,%7}, {%8,%9}, {%0,%1,%2,%3};\n"
        : "+f"(c[0]), "+f"(c[1]), "+f"(c[2]), "+f"(c[3])
        : "r"(a[0]), "r"(a[1]), "r"(a[2]), "r"(a[3]), "r"(b[0]), "r"(b[1]));
}

__device__ __forceinline__ void split2(float v, __nv_bfloat16& h, __nv_bfloat16& l) {
    h = __float2bfloat16_rn(v);
    l = __float2bfloat16_rn(v - __bfloat162float(h));
}

// ---------------------------------------------------------------------------
// Phase 1: complex matrix chain on tensor cores (bf16x3 split). R3-proven.
// ---------------------------------------------------------------------------
__global__ void __launch_bounds__(256)
chain_tc(const float* __restrict__ x_r, const float* __restrict__ x_i,
         const float* __restrict__ u_r, const float* __restrict__ u_i,
         const float* __restrict__ W_r, const float* __restrict__ W_i,
         float* __restrict__ feat)
{
    extern __shared__ __nv_bfloat16 smc[];
    __nv_bfloat16* sMrh = smc;
    __nv_bfloat16* sMrl = smc + 4096;
    __nv_bfloat16* sMih = smc + 8192;
    __nv_bfloat16* sMil = smc + 12288;
    __nv_bfloat16* sCrh = smc + 16384;
    __nv_bfloat16* sCrl = smc + 20480;
    __nv_bfloat16* sCih = smc + 24576;
    __nv_bfloat16* sCil = smc + 28672;

    const int tid = threadIdx.x;
    const int lane = tid & 31;
    const int warp = tid >> 5;
    const int b = blockIdx.x;

    const float* xr = x_r + (size_t)b * 8 * 4096;
    const float* xi = x_i + (size_t)b * 8 * 4096;

    #pragma unroll
    for (int j = 0; j < 4; j++) {
        int bi = warp + 8 * j;
        int nb = bi >> 2;
        int kb = bi & 3;
        int n  = nb * 8 + (lane >> 2);
        int k0 = kb * 16 + 2 * (lane & 3);
        int base = bi * 128 + lane * 4;
        float v0 = xr[k0 * 64 + n];
        float v1 = xr[(k0 + 1) * 64 + n];
        float v2 = xr[(k0 + 8) * 64 + n];
        float v3 = xr[(k0 + 9) * 64 + n];
        __nv_bfloat16 hh;
        __nv_bfloat16 ll;
        split2(v0, hh, ll);
        sCrh[base] = hh;
        sCrl[base] = ll;
        split2(v1, hh, ll);
        sCrh[base + 1] = hh;
        sCrl[base + 1] = ll;
        split2(v2, hh, ll);
        sCrh[base + 2] = hh;
        sCrl[base + 2] = ll;
        split2(v3, hh, ll);
        sCrh[base + 3] = hh;
        sCrl[base + 3] = ll;
        v0 = xi[k0 * 64 + n];
        v1 = xi[(k0 + 1) * 64 + n];
        v2 = xi[(k0 + 8) * 64 + n];
        v3 = xi[(k0 + 9) * 64 + n];
        split2(v0, hh, ll);
        sCih[base] = hh;
        sCil[base] = ll;
        split2(v1, hh, ll);
        sCih[base + 1] = hh;
        sCil[base + 1] = ll;
        split2(v2, hh, ll);
        sCih[base + 2] = hh;
        sCil[base + 2] = ll;
        split2(v3, hh, ll);
        sCih[base + 3] = hh;
        sCil[base + 3] = ll;
    }

    const int mb  = warp >> 1;
    const int nb0 = (warp & 1) * 4;

    float aDr1[4][4];
    float aDr2[4][4];
    float aDi[4][4];

    #pragma unroll 1
    for (int s = 0; s < 15; s++) {
        const float* Mr;
        const float* Mi;
        if (s & 1) {
            int li = (s + 1) >> 1;
            Mr = xr + li * 4096;
            Mi = xi + li * 4096;
        } else {
            int li = s >> 1;
            Mr = W_r + li * 4096;
            Mi = W_i + li * 4096;
        }

        #pragma unroll
        for (int j = 0; j < 2; j++) {
            int bi = warp + 8 * j;
            int mbl = bi >> 2;
            int kbl = bi & 3;
            int R  = mbl * 16 + (lane >> 2);
            int K0 = kbl * 16 + 2 * (lane & 3);
            int base = bi * 256 + lane * 8;
            float2 p0 = *(const float2*)&Mr[R * 64 + K0];
            float2 p1 = *(const float2*)&Mr[(R + 8) * 64 + K0];
            float2 p2 = *(const float2*)&Mr[R * 64 + K0 + 8];
            float2 p3 = *(const float2*)&Mr[(R + 8) * 64 + K0 + 8];
            __nv_bfloat16 hh;
            __nv_bfloat16 ll;
            split2(p0.x, hh, ll);
            sMrh[base] = hh;
            sMrl[base] = ll;
            split2(p0.y, hh, ll);
            sMrh[base + 1] = hh;
            sMrl[base + 1] = ll;
            split2(p1.x, hh, ll);
            sMrh[base + 2] = hh;
            sMrl[base + 2] = ll;
            split2(p1.y, hh, ll);
            sMrh[base + 3] = hh;
            sMrl[base + 3] = ll;
            split2(p2.x, hh, ll);
            sMrh[base + 4] = hh;
            sMrl[base + 4] = ll;
            split2(p2.y, hh, ll);
            sMrh[base + 5] = hh;
            sMrl[base + 5] = ll;
            split2(p3.x, hh, ll);
            sMrh[base + 6] = hh;
            sMrl[base + 6] = ll;
            split2(p3.y, hh, ll);
            sMrh[base + 7] = hh;
            sMrl[base + 7] = ll;
            p0 = *(const float2*)&Mi[R * 64 + K0];
            p1 = *(const float2*)&Mi[(R + 8) * 64 + K0];
            p2 = *(const float2*)&Mi[R * 64 + K0 + 8];
            p3 = *(const float2*)&Mi[(R + 8) * 64 + K0 + 8];
            split2(p0.x, hh, ll);
            sMih[base] = hh;
            sMil[base] = ll;
            split2(p0.y, hh, ll);
            sMih[base + 1] = hh;
            sMil[base + 1] = ll;
            split2(p1.x, hh, ll);
            sMih[base + 2] = hh;
            sMil[base + 2] = ll;
            split2(p1.y, hh, ll);
            sMih[base + 3] = hh;
            sMil[base + 3] = ll;
            split2(p2.x, hh, ll);
            sMih[base + 4] = hh;
            sMil[base + 4] = ll;
            split2(p2.y, hh, ll);
            sMih[base + 5] = hh;
            sMil[base + 5] = ll;
            split2(p3.x, hh, ll);
            sMih[base + 6] = hh;
            sMil[base + 6] = ll;
            split2(p3.y, hh, ll);
            sMih[base + 7] = hh;
            sMil[base + 7] = ll;
        }
        __syncthreads();

        #pragma unroll
        for (int g = 0; g < 4; g++) {
            #pragma unroll
            for (int v = 0; v < 4; v++) {
                aDr1[g][v] = 0.f;
                aDr2[g][v] = 0.f;
                aDi[g][v] = 0.f;
            }
        }

        #pragma unroll
        for (int kb = 0; kb < 4; kb++) {
            unsigned arh[4], arl[4], aih[4], ail[4];
            int abase = (mb * 4 + kb) * 256 + lane * 8;
            *(uint4*)arh = *(const uint4*)&sMrh[abase];
            *(uint4*)arl = *(const uint4*)&sMrl[abase];
            *(uint4*)aih = *(const uint4*)&sMih[abase];
            *(uint4*)ail = *(const uint4*)&sMil[abase];
            #pragma unroll
            for (int g = 0; g < 4; g++) {
                unsigned brh[2], brl[2], bih[2], bil[2];
                int bbase = ((nb0 + g) * 4 + kb) * 128 + lane * 4;
                *(uint2*)brh = *(const uint2*)&sCrh[bbase];
                *(uint2*)brl = *(const uint2*)&sCrl[bbase];
                *(uint2*)bih = *(const uint2*)&sCih[bbase];
                *(uint2*)bil = *(const uint2*)&sCil[bbase];
                mma_m16n8k16(aDr1[g], arh, brh);
                mma_m16n8k16(aDr1[g], arh, brl);
                mma_m16n8k16(aDr1[g], arl, brh);
                mma_m16n8k16(aDr2[g], aih, bih);
                mma_m16n8k16(aDr2[g], aih, bil);
                mma_m16n8k16(aDr2[g], ail, bih);
                mma_m16n8k16(aDi[g],  arh, bih);
                mma_m16n8k16(aDi[g],  arh, bil);
                mma_m16n8k16(aDi[g],  arl, bih);
                mma_m16n8k16(aDi[g],  aih, brh);
                mma_m16n8k16(aDi[g],  aih, brl);
                mma_m16n8k16(aDi[g],  ail, brh);
            }
        }
        __syncthreads();

        if (s < 14) {
            #pragma unroll
            for (int g = 0; g < 4; g++) {
                int rbase = (nb0 + g) * 8 + 2 * (lane & 3);
                #pragma unroll
                for (int ci = 0; ci < 4; ci++) {
                    int p = mb * 16 + (lane >> 2) + 8 * (ci >> 1);
                    int r = rbase + (ci & 1);
                    int nbp = r >> 3;
                    int kbp = p >> 4;
                    int lp = 4 * (r & 7) + ((p & 7) >> 1);
                    int addr = (nbp * 4 + kbp) * 128 + lp * 4 + (((p & 15) >= 8) ? 2 : 0) + (p & 1);
                    float vr = aDr1[g][ci] - aDr2[g][ci];
                    float vi = aDi[g][ci];
                    __nv_bfloat16 hh;
                    __nv_bfloat16 ll;
                    split2(vr, hh, ll);
                    sCrh[addr] = hh;
                    sCrl[addr] = ll;
                    split2(vi, hh, ll);
                    sCih[addr] = hh;
                    sCil[addr] = ll;
                }
            }
        }
    }

    const float* ur = u_r + (size_t)b * 4096;
    const float* ui = u_i + (size_t)b * 4096;
    float* fb = feat + (size_t)b * 8192;
    #pragma unroll
    for (int g = 0; g < 4; g++) {
        int r = (nb0 + g) * 8 + 2 * (lane & 3);
        #pragma unroll
        for (int hz = 0; hz < 2; hz++) {
            int p = mb * 16 + (lane >> 2) + 8 * hz;
            float2 u2 = *(const float2*)&ur[p * 64 + r];
            float2 o;
            o.x = u2.x - (aDr1[g][2 * hz]     - aDr2[g][2 * hz]);
            o.y = u2.y - (aDr1[g][2 * hz + 1] - aDr2[g][2 * hz + 1]);
            *(float2*)&fb[(p << 7) + r] = o;
            u2 = *(const float2*)&ui[p * 64 + r];
            o.x = u2.x - aDi[g][2 * hz];
            o.y = u2.y - aDi[g][2 * hz + 1];
            *(float2*)&fb[(p << 7) + 64 + r] = o;
        }
    }
}

// ---------------------------------------------------------------------------
// Prep: split fp32 -> bf16 h/l into A-fragment-major global layout.
// ---------------------------------------------------------------------------
__global__ void __launch_bounds__(256)
prep_a(const float* __restrict__ src, __nv_bfloat16* __restrict__ gh,
       __nv_bfloat16* __restrict__ gl, int K)
{
    __shared__ __nv_bfloat16 sh[4096];
    __shared__ __nv_bfloat16 sl[4096];
    const int tid = threadIdx.x;
    const int lrow = tid >> 1;
    const int kb2 = tid & 1;
    const int rA = lrow & 15;
    const int mbL = lrow >> 4;
    const int blk = mbL * 2 + kb2;
    const int a0 = blk * 256 + (rA & 7) * 32 + ((rA >> 3) << 1);
    const int NKC = K / 32;
    const float* srow = src + (size_t)(blockIdx.x * 128 + lrow) * K + kb2 * 16;

    for (int kc = blockIdx.y; kc < NKC; kc += gridDim.y) {
        #pragma unroll
        for (int ii = 0; ii < 4; ii++) {
            float4 v = *(const float4*)&srow[kc * 32 + ii * 4];
            int of = a0 + (((ii & 1) << 4) | ((ii >> 1) << 2));
            __nv_bfloat16 h0;
            __nv_bfloat16 l0;
            __nv_bfloat16 h1;
            __nv_bfloat16 l1;
            split2(v.x, h0, l0);
            split2(v.y, h1, l1);
            __nv_bfloat162 t;
            t.x = h0;
            t.y = h1;
            *(__nv_bfloat162*)&sh[of] = t;
            t.x = l0;
            t.y = l1;
            *(__nv_bfloat162*)&sl[of] = t;
            split2(v.z, h0, l0);
            split2(v.w, h1, l1);
            t.x = h0;
            t.y = h1;
            *(__nv_bfloat162*)&sh[of + 8] = t;
            t.x = l0;
            t.y = l1;
            *(__nv_bfloat162*)&sl[of + 8] = t;
        }
        __syncthreads();
        size_t ob = (size_t)(blockIdx.x * NKC + kc) * 4096;
        uint4* oh = (uint4*)(gh + ob);
        uint4* ol = (uint4*)(gl + ob);
        const uint4* ish = (const uint4*)sh;
        const uint4* isl = (const uint4*)sl;
        oh[tid] = ish[tid];
        oh[tid + 256] = ish[tid + 256];
        ol[tid] = isl[tid];
        ol[tid + 256] = isl[tid + 256];
        __syncthreads();
    }
}

// ---------------------------------------------------------------------------
// Prep: split fp32 -> bf16 h/l into PAIRED B-fragment-major global layout.
// Pair block (p = nb>>1, kk): 256 elems; lane*8 holds [4 elems nb=2p][4 of 2p+1].
// (R10-proven numerically.)
// ---------------------------------------------------------------------------
__global__ void __launch_bounds__(256)
prep_b(const float* __restrict__ src, __nv_bfloat16* __restrict__ gh,
       __nv_bfloat16* __restrict__ gl, int K)
{
    __shared__ __nv_bfloat16 sh[4096];
    __shared__ __nv_bfloat16 sl[4096];
    const int tid = threadIdx.x;
    const int lrow = tid >> 1;
    const int kb2 = tid & 1;
    const int pairIdx = lrow >> 4;          // nb >> 1
    const int odd = (lrow >> 3) & 1;        // nb & 1
    const int ncL = lrow & 7;
    const int blkbase = (pairIdx * 2 + kb2) * 256;
    const int NKC = K / 32;
    const float* srow = src + (size_t)(blockIdx.x * 128 + lrow) * K + kb2 * 16;

    for (int kc = blockIdx.y; kc < NKC; kc += gridDim.y) {
        #pragma unroll
        for (int ii = 0; ii < 4; ii++) {
            float4 v = *(const float4*)&srow[kc * 32 + ii * 4];
            int of_old = ncL * 16 + (((ii & 1) << 3) | ((ii >> 1) << 1));
            int nof = blkbase + (of_old >> 2) * 8 + odd * 4 + (of_old & 3);
            __nv_bfloat16 h0;
            __nv_bfloat16 l0;
            __nv_bfloat16 h1;
            __nv_bfloat16 l1;
            split2(v.x, h0, l0);
            split2(v.y, h1, l1);
            __nv_bfloat162 t;
            t.x = h0;
            t.y = h1;
            *(__nv_bfloat162*)&sh[nof] = t;
            t.x = l0;
            t.y = l1;
            *(__nv_bfloat162*)&sl[nof] = t;
            split2(v.z, h0, l0);
            split2(v.w, h1, l1);
            t.x = h0;
            t.y = h1;
            *(__nv_bfloat162*)&sh[nof + 8] = t;
            t.x = l0;
            t.y = l1;
            *(__nv_bfloat162*)&sl[nof + 8] = t;
        }
        __syncthreads();
        size_t ob = (size_t)(blockIdx.x * NKC + kc) * 4096;
        uint4* oh = (uint4*)(gh + ob);
        uint4* ol = (uint4*)(gl + ob);
        const uint4* ish = (const uint4*)sh;
        const uint4* isl = (const uint4*)sl;
        oh[tid] = ish[tid];
        oh[tid + 256] = ish[tid + 256];
        ol[tid] = isl[tid];
        ol[tid + 256] = isl[tid + 256];
        __syncthreads();
    }
}

// ---------------------------------------------------------------------------
// Phase 2: HMMA MLP GEMM v7 — A double-buffered in smem (32KB), B direct LDG
// from paired fragment layout (L1-served intra-CTA reuse). One sync per K32.
//   C[512,4096] = mish(A[512,K] @ W[4096,K]^T + bias)
// ---------------------------------------------------------------------------
template <int K>
__global__ void __launch_bounds__(256)
mlp_v7(const __nv_bfloat16* __restrict__ Ah, const __nv_bfloat16* __restrict__ Al,
       const __nv_bfloat16* __restrict__ Bh, const __nv_bfloat16* __restrict__ Bl,
       const float* __restrict__ bias, float* __restrict__ C)
{
    extern __shared__ __nv_bfloat16 smc[];
    const int NKC = K / 32;

    const int tid = threadIdx.x;
    const int lane = tid & 31;
    const int warp = tid >> 5;

    const uint4* pAh = (const uint4*)(Ah + (size_t)blockIdx.y * NKC * 4096);
    const uint4* pAl = (const uint4*)(Al + (size_t)blockIdx.y * NKC * 4096);
    const uint4* pBh = (const uint4*)(Bh + (size_t)blockIdx.x * NKC * 4096);
    const uint4* pBl = (const uint4*)(Bl + (size_t)blockIdx.x * NKC * 4096);

    const int mb0 = (warp >> 1) * 2;
    const int wn  = warp & 1;          // B pair group: pairs wn*4 .. wn*4+3

    float acc[2][8][4];
    #pragma unroll
    for (int f = 0; f < 2; f++)
        #pragma unroll
        for (int g = 0; g < 8; g++)
            #pragma unroll
            for (int v = 0; v < 4; v++) acc[f][g][v] = 0.f;

    uint4 rah0 = pAh[tid];
    uint4 rah1 = pAh[tid + 256];
    uint4 ral0 = pAl[tid];
    uint4 ral1 = pAl[tid + 256];

    #pragma unroll 1
    for (int kc = 0; kc < NKC; kc++) {
        __nv_bfloat16* st = smc + (kc & 1) * 8192;
        uint4* s4 = (uint4*)st;
        // stage layout (uint4): Ah [0,512), Al [512,1024)
        s4[tid] = rah0;
        s4[tid + 256] = rah1;
        s4[512 + tid] = ral0;
        s4[512 + tid + 256] = ral1;
        __syncthreads();

        if (kc + 1 < NKC) {
            int o = (kc + 1) * 512 + tid;
            rah0 = pAh[o];
            rah1 = pAh[o + 256];
            ral0 = pAl[o];
            ral1 = pAl[o + 256];
        }

        const __nv_bfloat16* sAh = st;
        const __nv_bfloat16* sAl = st + 4096;

        #pragma unroll
        for (int kk = 0; kk < 2; kk++) {
            unsigned ah[2][4], al[2][4];
            #pragma unroll
            for (int f = 0; f < 2; f++) {
                int base = ((mb0 + f) * 2 + kk) * 256 + lane * 8;
                *(uint4*)ah[f] = *(const uint4*)&sAh[base];
                *(uint4*)al[f] = *(const uint4*)&sAl[base];
            }
            #pragma unroll
            for (int p = 0; p < 4; p++) {
                int bi = kc * 512 + ((wn * 4 + p) * 2 + kk) * 32 + lane;
                uint4 ubh = __ldg(&pBh[bi]);
                uint4 ubl = __ldg(&pBl[bi]);
                unsigned bh0[2], bl0[2], bh1[2], bl1[2];
                bh0[0] = ubh.x; bh0[1] = ubh.y;
                bh1[0] = ubh.z; bh1[1] = ubh.w;
                bl0[0] = ubl.x; bl0[1] = ubl.y;
                bl1[0] = ubl.z; bl1[1] = ubl.w;
                #pragma unroll
                for (int f = 0; f < 2; f++) {
                    mma_m16n8k16(acc[f][2 * p],     ah[f], bh0);
                    mma_m16n8k16(acc[f][2 * p],     ah[f], bl0);
                    mma_m16n8k16(acc[f][2 * p],     al[f], bh0);
                    mma_m16n8k16(acc[f][2 * p + 1], ah[f], bh1);
                    mma_m16n8k16(acc[f][2 * p + 1], ah[f], bl1);
                    mma_m16n8k16(acc[f][2 * p + 1], al[f], bh1);
                }
            }
        }
        // stage (kc&1) rewritten only at kc+2, after the kc+1 barrier.
    }

    const int row0  = blockIdx.y * 128 + (warp >> 1) * 32 + (lane >> 2);
    const int col00 = blockIdx.x * 128 + wn * 64 + (lane & 3) * 2;
    #pragma unroll
    for (int f = 0; f < 2; f++) {
        #pragma unroll
        for (int g = 0; g < 8; g++) {
            int c = col00 + g * 8;
            float b0 = __ldg(&bias[c]);
            float b1 = __ldg(&bias[c + 1]);
            #pragma unroll
            for (int hz = 0; hz < 2; hz++) {
                int r = row0 + f * 16 + hz * 8;
                float2 o;
                o.x = mishf(acc[f][g][2 * hz]     + b0);
                o.y = mishf(acc[f][g][2 * hz + 1] + b1);
                *(float2*)&C[(size_t)r * 4096 + c] = o;
            }
        }
    }
}

// ---------------------------------------------------------------------------
// Phase 3: out[b] = h2[b,:] . w3 + b3
// ---------------------------------------------------------------------------
__global__ void final_kernel(const float* __restrict__ H,
                             const float* __restrict__ w3,
                             const float* __restrict__ b3,
                             float* __restrict__ out)
{
    const int b = blockIdx.x;
    const float* h = H + (size_t)b * 4096;
    float s = 0.f;
    for (int i = threadIdx.x; i < 4096; i += 256) {
        s = fmaf(h[i], w3[i], s);
    }
    #pragma unroll
    for (int o = 16; o > 0; o >>= 1) {
        s += __shfl_down_sync(0xffffffffu, s, o);
    }
    __shared__ float red[8];
    if ((threadIdx.x & 31) == 0) {
        red[threadIdx.x >> 5] = s;
    }
    __syncthreads();
    if (threadIdx.x == 0) {
        float t = 0.f;
        #pragma unroll
        for (int i = 0; i < 8; i++) {
            t += red[i];
        }
        out[b] = t + b3[0];
    }
}

// ---------------------------------------------------------------------------
extern "C" void kernel_launch(void* const* d_in, const int* in_sizes, int n_in,
                              void* d_out, int out_size)
{
    const float* x_r = (const float*)d_in[0];
    const float* x_i = (const float*)d_in[1];
    const float* u_r = (const float*)d_in[2];
    const float* u_i = (const float*)d_in[3];
    const float* W_r = (const float*)d_in[4];
    const float* W_i = (const float*)d_in[5];
    const float* w1  = (const float*)d_in[6];
    const float* b1  = (const float*)d_in[7];
    const float* w2  = (const float*)d_in[8];
    const float* b2  = (const float*)d_in[9];
    const float* w3  = (const float*)d_in[10];
    const float* b3  = (const float*)d_in[11];
    float* out = (float*)d_out;

    float* feat;
    float* h1;
    float* h2;
    cudaGetSymbolAddress((void**)&feat, g_feat);
    cudaGetSymbolAddress((void**)&h1, g_h1);
    cudaGetSymbolAddress((void**)&h2, g_h2);

    __nv_bfloat16* fah;
    __nv_bfloat16* fal;
    __nv_bfloat16* h1ah;
    __nv_bfloat16* h1al;
    __nv_bfloat16* w1h;
    __nv_bfloat16* w1l;
    __nv_bfloat16* w2h;
    __nv_bfloat16* w2l;
    cudaGetSymbolAddress((void**)&fah, g_fah);
    cudaGetSymbolAddress((void**)&fal, g_fal);
    cudaGetSymbolAddress((void**)&h1ah, g_h1ah);
    cudaGetSymbolAddress((void**)&h1al, g_h1al);
    cudaGetSymbolAddress((void**)&w1h, g_w1h);
    cudaGetSymbolAddress((void**)&w1l, g_w1l);
    cudaGetSymbolAddress((void**)&w2h, g_w2h);
    cudaGetSymbolAddress((void**)&w2l, g_w2l);

    cudaFuncSetAttribute((const void*)chain_tc,
                         cudaFuncAttributeMaxDynamicSharedMemorySize, 65536);

    prep_b<<<dim3(32, 32), 256>>>(w1, w1h, w1l, 8192);
    prep_b<<<dim3(32, 32), 256>>>(w2, w2h, w2l, 4096);
    chain_tc<<<512, 256, 65536>>>(x_r, x_i, u_r, u_i, W_r, W_i, feat);
    prep_a<<<dim3(4, 64), 256>>>(feat, fah, fal, 8192);
    mlp_v7<8192><<<dim3(32, 4), 256, 32768>>>(fah, fal, w1h, w1l, b1, h1);
    prep_a<<<dim3(4, 64), 256>>>(h1, h1ah, h1al, 4096);
    mlp_v7<4096><<<dim3(32, 4), 256, 32768>>>(h1ah, h1al, w2h, w2l, b2, h2);
    final_kernel<<<512, 256>>>(h2, w3, b3, out);
}

// round 14
// speedup vs baseline: 2.3611x; 2.3611x over previous
#include <cuda_runtime.h>
#include <cuda_bf16.h>
#include <math.h>

// ---------------- scratch (device globals: allocation-free rule) -------------
__device__ float g_feat[512 * 8192];   // chain output features
__device__ float g_h1[512 * 4096];     // MLP hidden 1
__device__ float g_h2[512 * 4096];     // MLP hidden 2

// pre-split fragment-major bf16 buffers (hi / lo residual)
__device__ __nv_bfloat16 g_fah[512 * 8192];
__device__ __nv_bfloat16 g_fal[512 * 8192];
__device__ __nv_bfloat16 g_h1ah[512 * 4096];
__device__ __nv_bfloat16 g_h1al[512 * 4096];
__device__ __nv_bfloat16 g_w1h[4096 * 8192];
__device__ __nv_bfloat16 g_w1l[4096 * 8192];
__device__ __nv_bfloat16 g_w2h[4096 * 4096];
__device__ __nv_bfloat16 g_w2l[4096 * 4096];

__device__ __forceinline__ float mishf(float x) {
    float sp = (x > 20.f) ? x : log1pf(expf(x));
    return x * tanhf(sp);
}

__device__ __forceinline__ void mma_m16n8k16(float c[4], const unsigned a[4], const unsigned b[2]) {
    asm volatile(
        "mma.sync.aligned.m16n8k16.row.col.f32.bf16.bf16.f32 "
        "{%0,%1,%2,%3}, {%4,%5,%6,%7}, {%8,%9}, {%0,%1,%2,%3};\n"
        : "+f"(c[0]), "+f"(c[1]), "+f"(c[2]), "+f"(c[3])
        : "r"(a[0]), "r"(a[1]), "r"(a[2]), "r"(a[3]), "r"(b[0]), "r"(b[1]));
}

__device__ __forceinline__ void split2(float v, __nv_bfloat16& h, __nv_bfloat16& l) {
    h = __float2bfloat16_rn(v);
    l = __float2bfloat16_rn(v - __bfloat162float(h));
}

// ---------------------------------------------------------------------------
// Chain body (R3-proven). One call = one batch element b. Uses 64KB of smc.
// ---------------------------------------------------------------------------
__device__ void chain_body(const float* __restrict__ x_r, const float* __restrict__ x_i,
                           const float* __restrict__ u_r, const float* __restrict__ u_i,
                           const float* __restrict__ W_r, const float* __restrict__ W_i,
                           float* __restrict__ feat, __nv_bfloat16* smc, int b)
{
    __nv_bfloat16* sMrh = smc;
    __nv_bfloat16* sMrl = smc + 4096;
    __nv_bfloat16* sMih = smc + 8192;
    __nv_bfloat16* sMil = smc + 12288;
    __nv_bfloat16* sCrh = smc + 16384;
    __nv_bfloat16* sCrl = smc + 20480;
    __nv_bfloat16* sCih = smc + 24576;
    __nv_bfloat16* sCil = smc + 28672;

    const int tid = threadIdx.x;
    const int lane = tid & 31;
    const int warp = tid >> 5;

    const float* xr = x_r + (size_t)b * 8 * 4096;
    const float* xi = x_i + (size_t)b * 8 * 4096;

    #pragma unroll
    for (int j = 0; j < 4; j++) {
        int bi = warp + 8 * j;
        int nb = bi >> 2;
        int kb = bi & 3;
        int n  = nb * 8 + (lane >> 2);
        int k0 = kb * 16 + 2 * (lane & 3);
        int base = bi * 128 + lane * 4;
        float v0 = xr[k0 * 64 + n];
        float v1 = xr[(k0 + 1) * 64 + n];
        float v2 = xr[(k0 + 8) * 64 + n];
        float v3 = xr[(k0 + 9) * 64 + n];
        __nv_bfloat16 hh;
        __nv_bfloat16 ll;
        split2(v0, hh, ll);
        sCrh[base] = hh;
        sCrl[base] = ll;
        split2(v1, hh, ll);
        sCrh[base + 1] = hh;
        sCrl[base + 1] = ll;
        split2(v2, hh, ll);
        sCrh[base + 2] = hh;
        sCrl[base + 2] = ll;
        split2(v3, hh, ll);
        sCrh[base + 3] = hh;
        sCrl[base + 3] = ll;
        v0 = xi[k0 * 64 + n];
        v1 = xi[(k0 + 1) * 64 + n];
        v2 = xi[(k0 + 8) * 64 + n];
        v3 = xi[(k0 + 9) * 64 + n];
        split2(v0, hh, ll);
        sCih[base] = hh;
        sCil[base] = ll;
        split2(v1, hh, ll);
        sCih[base + 1] = hh;
        sCil[base + 1] = ll;
        split2(v2, hh, ll);
        sCih[base + 2] = hh;
        sCil[base + 2] = ll;
        split2(v3, hh, ll);
        sCih[base + 3] = hh;
        sCil[base + 3] = ll;
    }

    const int mb  = warp >> 1;
    const int nb0 = (warp & 1) * 4;

    float aDr1[4][4];
    float aDr2[4][4];
    float aDi[4][4];

    #pragma unroll 1
    for (int s = 0; s < 15; s++) {
        const float* Mr;
        const float* Mi;
        if (s & 1) {
            int li = (s + 1) >> 1;
            Mr = xr + li * 4096;
            Mi = xi + li * 4096;
        } else {
            int li = s >> 1;
            Mr = W_r + li * 4096;
            Mi = W_i + li * 4096;
        }

        #pragma unroll
        for (int j = 0; j < 2; j++) {
            int bi = warp + 8 * j;
            int mbl = bi >> 2;
            int kbl = bi & 3;
            int R  = mbl * 16 + (lane >> 2);
            int K0 = kbl * 16 + 2 * (lane & 3);
            int base = bi * 256 + lane * 8;
            float2 p0 = *(const float2*)&Mr[R * 64 + K0];
            float2 p1 = *(const float2*)&Mr[(R + 8) * 64 + K0];
            float2 p2 = *(const float2*)&Mr[R * 64 + K0 + 8];
            float2 p3 = *(const float2*)&Mr[(R + 8) * 64 + K0 + 8];
            __nv_bfloat16 hh;
            __nv_bfloat16 ll;
            split2(p0.x, hh, ll);
            sMrh[base] = hh;
            sMrl[base] = ll;
            split2(p0.y, hh, ll);
            sMrh[base + 1] = hh;
            sMrl[base + 1] = ll;
            split2(p1.x, hh, ll);
            sMrh[base + 2] = hh;
            sMrl[base + 2] = ll;
            split2(p1.y, hh, ll);
            sMrh[base + 3] = hh;
            sMrl[base + 3] = ll;
            split2(p2.x, hh, ll);
            sMrh[base + 4] = hh;
            sMrl[base + 4] = ll;
            split2(p2.y, hh, ll);
            sMrh[base + 5] = hh;
            sMrl[base + 5] = ll;
            split2(p3.x, hh, ll);
            sMrh[base + 6] = hh;
            sMrl[base + 6] = ll;
            split2(p3.y, hh, ll);
            sMrh[base + 7] = hh;
            sMrl[base + 7] = ll;
            p0 = *(const float2*)&Mi[R * 64 + K0];
            p1 = *(const float2*)&Mi[(R + 8) * 64 + K0];
            p2 = *(const float2*)&Mi[R * 64 + K0 + 8];
            p3 = *(const float2*)&Mi[(R + 8) * 64 + K0 + 8];
            split2(p0.x, hh, ll);
            sMih[base] = hh;
            sMil[base] = ll;
            split2(p0.y, hh, ll);
            sMih[base + 1] = hh;
            sMil[base + 1] = ll;
            split2(p1.x, hh, ll);
            sMih[base + 2] = hh;
            sMil[base + 2] = ll;
            split2(p1.y, hh, ll);
            sMih[base + 3] = hh;
            sMil[base + 3] = ll;
            split2(p2.x, hh, ll);
            sMih[base + 4] = hh;
            sMil[base + 4] = ll;
            split2(p2.y, hh, ll);
            sMih[base + 5] = hh;
            sMil[base + 5] = ll;
            split2(p3.x, hh, ll);
            sMih[base + 6] = hh;
            sMil[base + 6] = ll;
            split2(p3.y, hh, ll);
            sMih[base + 7] = hh;
            sMil[base + 7] = ll;
        }
        __syncthreads();

        #pragma unroll
        for (int g = 0; g < 4; g++) {
            #pragma unroll
            for (int v = 0; v < 4; v++) {
                aDr1[g][v] = 0.f;
                aDr2[g][v] = 0.f;
                aDi[g][v] = 0.f;
            }
        }

        #pragma unroll
        for (int kb = 0; kb < 4; kb++) {
            unsigned arh[4], arl[4], aih[4], ail[4];
            int abase = (mb * 4 + kb) * 256 + lane * 8;
            *(uint4*)arh = *(const uint4*)&sMrh[abase];
            *(uint4*)arl = *(const uint4*)&sMrl[abase];
            *(uint4*)aih = *(const uint4*)&sMih[abase];
            *(uint4*)ail = *(const uint4*)&sMil[abase];
            #pragma unroll
            for (int g = 0; g < 4; g++) {
                unsigned brh[2], brl[2], bih[2], bil[2];
                int bbase = ((nb0 + g) * 4 + kb) * 128 + lane * 4;
                *(uint2*)brh = *(const uint2*)&sCrh[bbase];
                *(uint2*)brl = *(const uint2*)&sCrl[bbase];
                *(uint2*)bih = *(const uint2*)&sCih[bbase];
                *(uint2*)bil = *(const uint2*)&sCil[bbase];
                mma_m16n8k16(aDr1[g], arh, brh);
                mma_m16n8k16(aDr1[g], arh, brl);
                mma_m16n8k16(aDr1[g], arl, brh);
                mma_m16n8k16(aDr2[g], aih, bih);
                mma_m16n8k16(aDr2[g], aih, bil);
                mma_m16n8k16(aDr2[g], ail, bih);
                mma_m16n8k16(aDi[g],  arh, bih);
                mma_m16n8k16(aDi[g],  arh, bil);
                mma_m16n8k16(aDi[g],  arl, bih);
                mma_m16n8k16(aDi[g],  aih, brh);
                mma_m16n8k16(aDi[g],  aih, brl);
                mma_m16n8k16(aDi[g],  ail, brh);
            }
        }
        __syncthreads();

        if (s < 14) {
            #pragma unroll
            for (int g = 0; g < 4; g++) {
                int rbase = (nb0 + g) * 8 + 2 * (lane & 3);
                #pragma unroll
                for (int ci = 0; ci < 4; ci++) {
                    int p = mb * 16 + (lane >> 2) + 8 * (ci >> 1);
                    int r = rbase + (ci & 1);
                    int nbp = r >> 3;
                    int kbp = p >> 4;
                    int lp = 4 * (r & 7) + ((p & 7) >> 1);
                    int addr = (nbp * 4 + kbp) * 128 + lp * 4 + (((p & 15) >= 8) ? 2 : 0) + (p & 1);
                    float vr = aDr1[g][ci] - aDr2[g][ci];
                    float vi = aDi[g][ci];
                    __nv_bfloat16 hh;
                    __nv_bfloat16 ll;
                    split2(vr, hh, ll);
                    sCrh[addr] = hh;
                    sCrl[addr] = ll;
                    split2(vi, hh, ll);
                    sCih[addr] = hh;
                    sCil[addr] = ll;
                }
            }
        }
    }

    const float* ur = u_r + (size_t)b * 4096;
    const float* ui = u_i + (size_t)b * 4096;
    float* fb = feat + (size_t)b * 8192;
    #pragma unroll
    for (int g = 0; g < 4; g++) {
        int r = (nb0 + g) * 8 + 2 * (lane & 3);
        #pragma unroll
        for (int hz = 0; hz < 2; hz++) {
            int p = mb * 16 + (lane >> 2) + 8 * hz;
            float2 u2 = *(const float2*)&ur[p * 64 + r];
            float2 o;
            o.x = u2.x - (aDr1[g][2 * hz]     - aDr2[g][2 * hz]);
            o.y = u2.y - (aDr1[g][2 * hz + 1] - aDr2[g][2 * hz + 1]);
            *(float2*)&fb[(p << 7) + r] = o;
            u2 = *(const float2*)&ui[p * 64 + r];
            o.x = u2.x - aDi[g][2 * hz];
            o.y = u2.y - aDi[g][2 * hz + 1];
            *(float2*)&fb[(p << 7) + 64 + r] = o;
        }
    }
}

// ---------------------------------------------------------------------------
// prep_b body (R12-proven), parametrized by block coords; uses 16KB of smc.
// ---------------------------------------------------------------------------
__device__ void prep_b_body(const float* __restrict__ src, __nv_bfloat16* __restrict__ gh,
                            __nv_bfloat16* __restrict__ gl, int K,
                            int bx, int by, int gy, __nv_bfloat16* smc)
{
    __nv_bfloat16* sh = smc;
    __nv_bfloat16* sl = smc + 4096;
    const int tid = threadIdx.x;
    const int lrow = tid >> 1;
    const int kb2 = tid & 1;
    const int nbL = lrow >> 3;
    const int ncL = lrow & 7;
    const int blk = nbL * 2 + kb2;
    const int a0 = blk * 128 + ncL * 16;
    const int NKC = K / 32;
    const float* srow = src + (size_t)(bx * 128 + lrow) * K + kb2 * 16;

    for (int kc = by; kc < NKC; kc += gy) {
        #pragma unroll
        for (int ii = 0; ii < 4; ii++) {
            float4 v = *(const float4*)&srow[kc * 32 + ii * 4];
            int of = a0 + (((ii & 1) << 3) | ((ii >> 1) << 1));
            __nv_bfloat16 h0;
            __nv_bfloat16 l0;
            __nv_bfloat16 h1;
            __nv_bfloat16 l1;
            split2(v.x, h0, l0);
            split2(v.y, h1, l1);
            __nv_bfloat162 t;
            t.x = h0;
            t.y = h1;
            *(__nv_bfloat162*)&sh[of] = t;
            t.x = l0;
            t.y = l1;
            *(__nv_bfloat162*)&sl[of] = t;
            split2(v.z, h0, l0);
            split2(v.w, h1, l1);
            t.x = h0;
            t.y = h1;
            *(__nv_bfloat162*)&sh[of + 4] = t;
            t.x = l0;
            t.y = l1;
            *(__nv_bfloat162*)&sl[of + 4] = t;
        }
        __syncthreads();
        size_t ob = (size_t)(bx * NKC + kc) * 4096;
        uint4* oh = (uint4*)(gh + ob);
        uint4* ol = (uint4*)(gl + ob);
        const uint4* ish = (const uint4*)sh;
        const uint4* isl = (const uint4*)sl;
        oh[tid] = ish[tid];
        oh[tid + 256] = ish[tid + 256];
        ol[tid] = isl[tid];
        ol[tid + 256] = isl[tid + 256];
        __syncthreads();
    }
}

// ---------------------------------------------------------------------------
// Fused kernel: interleaved [chain, w1-prep, w1-prep, w2-prep] per 4 CTAs.
// grid = 2048 CTAs. Overlaps DRAM-bound weight prep with compute-bound chain.
// ---------------------------------------------------------------------------
__global__ void __launch_bounds__(256)
fused_chain_prep(const float* __restrict__ x_r, const float* __restrict__ x_i,
                 const float* __restrict__ u_r, const float* __restrict__ u_i,
                 const float* __restrict__ W_r, const float* __restrict__ W_i,
                 float* __restrict__ feat,
                 const float* __restrict__ w1, __nv_bfloat16* __restrict__ w1h,
                 __nv_bfloat16* __restrict__ w1l,
                 const float* __restrict__ w2, __nv_bfloat16* __restrict__ w2h,
                 __nv_bfloat16* __restrict__ w2l)
{
    extern __shared__ __nv_bfloat16 smc[];
    const int bid = blockIdx.x;
    const int sel = bid & 3;
    const int grp = bid >> 2;          // 0..511
    if (sel == 0) {
        chain_body(x_r, x_i, u_r, u_i, W_r, W_i, feat, smc, grp);
    } else if (sel == 3) {
        // w2: 512 virtual CTAs -> bx 0..31, by 0..15 (gy=16)
        prep_b_body(w2, w2h, w2l, 4096, grp & 31, grp >> 5, 16, smc);
    } else {
        // w1: 1024 virtual CTAs -> idx 0..1023, bx 0..31, by 0..31 (gy=32)
        int idx = grp * 2 + (sel - 1);
        prep_b_body(w1, w1h, w1l, 8192, idx & 31, idx >> 5, 32, smc);
    }
}

// ---------------------------------------------------------------------------
// Prep: split fp32 -> bf16 h/l into A-fragment-major global layout.
// ---------------------------------------------------------------------------
__global__ void __launch_bounds__(256)
prep_a(const float* __restrict__ src, __nv_bfloat16* __restrict__ gh,
       __nv_bfloat16* __restrict__ gl, int K)
{
    __shared__ __nv_bfloat16 sh[4096];
    __shared__ __nv_bfloat16 sl[4096];
    const int tid = threadIdx.x;
    const int lrow = tid >> 1;
    const int kb2 = tid & 1;
    const int rA = lrow & 15;
    const int mbL = lrow >> 4;
    const int blk = mbL * 2 + kb2;
    const int a0 = blk * 256 + (rA & 7) * 32 + ((rA >> 3) << 1);
    const int NKC = K / 32;
    const float* srow = src + (size_t)(blockIdx.x * 128 + lrow) * K + kb2 * 16;

    for (int kc = blockIdx.y; kc < NKC; kc += gridDim.y) {
        #pragma unroll
        for (int ii = 0; ii < 4; ii++) {
            float4 v = *(const float4*)&srow[kc * 32 + ii * 4];
            int of = a0 + (((ii & 1) << 4) | ((ii >> 1) << 2));
            __nv_bfloat16 h0;
            __nv_bfloat16 l0;
            __nv_bfloat16 h1;
            __nv_bfloat16 l1;
            split2(v.x, h0, l0);
            split2(v.y, h1, l1);
            __nv_bfloat162 t;
            t.x = h0;
            t.y = h1;
            *(__nv_bfloat162*)&sh[of] = t;
            t.x = l0;
            t.y = l1;
            *(__nv_bfloat162*)&sl[of] = t;
            split2(v.z, h0, l0);
            split2(v.w, h1, l1);
            t.x = h0;
            t.y = h1;
            *(__nv_bfloat162*)&sh[of + 8] = t;
            t.x = l0;
            t.y = l1;
            *(__nv_bfloat162*)&sl[of + 8] = t;
        }
        __syncthreads();
        size_t ob = (size_t)(blockIdx.x * NKC + kc) * 4096;
        uint4* oh = (uint4*)(gh + ob);
        uint4* ol = (uint4*)(gl + ob);
        const uint4* ish = (const uint4*)sh;
        const uint4* isl = (const uint4*)sl;
        oh[tid] = ish[tid];
        oh[tid + 256] = ish[tid + 256];
        ol[tid] = isl[tid];
        ol[tid + 256] = isl[tid + 256];
        __syncthreads();
    }
}

// ---------------------------------------------------------------------------
// Phase 2: HMMA MLP GEMM v6 (R12-proven) — 128x128 tile, double-buffered smem,
// one __syncthreads per K32 iteration.
// ---------------------------------------------------------------------------
template <int K>
__global__ void __launch_bounds__(256)
mlp_v6(const __nv_bfloat16* __restrict__ Ah, const __nv_bfloat16* __restrict__ Al,
       const __nv_bfloat16* __restrict__ Bh, const __nv_bfloat16* __restrict__ Bl,
       const float* __restrict__ bias, float* __restrict__ C)
{
    extern __shared__ __nv_bfloat16 smc[];
    const int NKC = K / 32;

    const int tid = threadIdx.x;
    const int lane = tid & 31;
    const int warp = tid >> 5;

    const uint4* pAh = (const uint4*)(Ah + (size_t)blockIdx.y * NKC * 4096);
    const uint4* pAl = (const uint4*)(Al + (size_t)blockIdx.y * NKC * 4096);
    const uint4* pBh = (const uint4*)(Bh + (size_t)blockIdx.x * NKC * 4096);
    const uint4* pBl = (const uint4*)(Bl + (size_t)blockIdx.x * NKC * 4096);

    const int mb0 = (warp >> 1) * 2;
    const int nb0 = (warp & 1) * 8;

    float acc[2][8][4];
    #pragma unroll
    for (int f = 0; f < 2; f++)
        #pragma unroll
        for (int g = 0; g < 8; g++)
            #pragma unroll
            for (int v = 0; v < 4; v++) acc[f][g][v] = 0.f;

    uint4 rah0 = pAh[tid];
    uint4 rah1 = pAh[tid + 256];
    uint4 ral0 = pAl[tid];
    uint4 ral1 = pAl[tid + 256];
    uint4 rbh0 = pBh[tid];
    uint4 rbh1 = pBh[tid + 256];
    uint4 rbl0 = pBl[tid];
    uint4 rbl1 = pBl[tid + 256];

    #pragma unroll 1
    for (int kc = 0; kc < NKC; kc++) {
        __nv_bfloat16* st = smc + (kc & 1) * 16384;
        uint4* s4 = (uint4*)st;
        s4[tid] = rah0;
        s4[tid + 256] = rah1;
        s4[512 + tid] = ral0;
        s4[512 + tid + 256] = ral1;
        s4[1024 + tid] = rbh0;
        s4[1024 + tid + 256] = rbh1;
        s4[1536 + tid] = rbl0;
        s4[1536 + tid + 256] = rbl1;
        __syncthreads();

        if (kc + 1 < NKC) {
            int o = (kc + 1) * 512 + tid;
            rah0 = pAh[o];
            rah1 = pAh[o + 256];
            ral0 = pAl[o];
            ral1 = pAl[o + 256];
            rbh0 = pBh[o];
            rbh1 = pBh[o + 256];
            rbl0 = pBl[o];
            rbl1 = pBl[o + 256];
        }

        const __nv_bfloat16* sAh = st;
        const __nv_bfloat16* sAl = st + 4096;
        const __nv_bfloat16* sBh = st + 8192;
        const __nv_bfloat16* sBl = st + 12288;

        #pragma unroll
        for (int kk = 0; kk < 2; kk++) {
            unsigned ah[2][4], al[2][4];
            #pragma unroll
            for (int f = 0; f < 2; f++) {
                int base = ((mb0 + f) * 2 + kk) * 256 + lane * 8;
                *(uint4*)ah[f] = *(const uint4*)&sAh[base];
                *(uint4*)al[f] = *(const uint4*)&sAl[base];
            }
            #pragma unroll
            for (int g = 0; g < 8; g++) {
                unsigned bh[2], bl[2];
                int base = ((nb0 + g) * 2 + kk) * 128 + lane * 4;
                *(uint2*)bh = *(const uint2*)&sBh[base];
                *(uint2*)bl = *(const uint2*)&sBl[base];
                #pragma unroll
                for (int f = 0; f < 2; f++) {
                    mma_m16n8k16(acc[f][g], ah[f], bh);
                    mma_m16n8k16(acc[f][g], ah[f], bl);
                    mma_m16n8k16(acc[f][g], al[f], bh);
                }
            }
        }
    }

    const int row0  = blockIdx.y * 128 + (warp >> 1) * 32 + (lane >> 2);
    const int col00 = blockIdx.x * 128 + (warp & 1) * 64 + (lane & 3) * 2;
    #pragma unroll
    for (int f = 0; f < 2; f++) {
        #pragma unroll
        for (int g = 0; g < 8; g++) {
            int c = col00 + g * 8;
            float b0 = __ldg(&bias[c]);
            float b1 = __ldg(&bias[c + 1]);
            #pragma unroll
            for (int hz = 0; hz < 2; hz++) {
                int r = row0 + f * 16 + hz * 8;
                float2 o;
                o.x = mishf(acc[f][g][2 * hz]     + b0);
                o.y = mishf(acc[f][g][2 * hz + 1] + b1);
                *(float2*)&C[(size_t)r * 4096 + c] = o;
            }
        }
    }
}

// ---------------------------------------------------------------------------
// Phase 3: out[b] = h2[b,:] . w3 + b3
// ---------------------------------------------------------------------------
__global__ void final_kernel(const float* __restrict__ H,
                             const float* __restrict__ w3,
                             const float* __restrict__ b3,
                             float* __restrict__ out)
{
    const int b = blockIdx.x;
    const float* h = H + (size_t)b * 4096;
    float s = 0.f;
    for (int i = threadIdx.x; i < 4096; i += 256) {
        s = fmaf(h[i], w3[i], s);
    }
    #pragma unroll
    for (int o = 16; o > 0; o >>= 1) {
        s += __shfl_down_sync(0xffffffffu, s, o);
    }
    __shared__ float red[8];
    if ((threadIdx.x & 31) == 0) {
        red[threadIdx.x >> 5] = s;
    }
    __syncthreads();
    if (threadIdx.x == 0) {
        float t = 0.f;
        #pragma unroll
        for (int i = 0; i < 8; i++) {
            t += red[i];
        }
        out[b] = t + b3[0];
    }
}

// ---------------------------------------------------------------------------
extern "C" void kernel_launch(void* const* d_in, const int* in_sizes, int n_in,
                              void* d_out, int out_size)
{
    const float* x_r = (const float*)d_in[0];
    const float* x_i = (const float*)d_in[1];
    const float* u_r = (const float*)d_in[2];
    const float* u_i = (const float*)d_in[3];
    const float* W_r = (const float*)d_in[4];
    const float* W_i = (const float*)d_in[5];
    const float* w1  = (const float*)d_in[6];
    const float* b1  = (const float*)d_in[7];
    const float* w2  = (const float*)d_in[8];
    const float* b2  = (const float*)d_in[9];
    const float* w3  = (const float*)d_in[10];
    const float* b3  = (const float*)d_in[11];
    float* out = (float*)d_out;

    float* feat;
    float* h1;
    float* h2;
    cudaGetSymbolAddress((void**)&feat, g_feat);
    cudaGetSymbolAddress((void**)&h1, g_h1);
    cudaGetSymbolAddress((void**)&h2, g_h2);

    __nv_bfloat16* fah;
    __nv_bfloat16* fal;
    __nv_bfloat16* h1ah;
    __nv_bfloat16* h1al;
    __nv_bfloat16* w1h;
    __nv_bfloat16* w1l;
    __nv_bfloat16* w2h;
    __nv_bfloat16* w2l;
    cudaGetSymbolAddress((void**)&fah, g_fah);
    cudaGetSymbolAddress((void**)&fal, g_fal);
    cudaGetSymbolAddress((void**)&h1ah, g_h1ah);
    cudaGetSymbolAddress((void**)&h1al, g_h1al);
    cudaGetSymbolAddress((void**)&w1h, g_w1h);
    cudaGetSymbolAddress((void**)&w1l, g_w1l);
    cudaGetSymbolAddress((void**)&w2h, g_w2h);
    cudaGetSymbolAddress((void**)&w2l, g_w2l);

    cudaFuncSetAttribute((const void*)fused_chain_prep,
                         cudaFuncAttributeMaxDynamicSharedMemorySize, 65536);
    cudaFuncSetAttribute((const void*)mlp_v6<8192>,
                         cudaFuncAttributeMaxDynamicSharedMemorySize, 65536);
    cudaFuncSetAttribute((const void*)mlp_v6<4096>,
                         cudaFuncAttributeMaxDynamicSharedMemorySize, 65536);

    fused_chain_prep<<<2048, 256, 65536>>>(x_r, x_i, u_r, u_i, W_r, W_i, feat,
                                           w1, w1h, w1l, w2, w2h, w2l);
    prep_a<<<dim3(4, 64), 256>>>(feat, fah, fal, 8192);
    mlp_v6<8192><<<dim3(32, 4), 256, 65536>>>(fah, fal, w1h, w1l, b1, h1);
    prep_a<<<dim3(4, 64), 256>>>(h1, h1ah, h1al, 4096);
    mlp_v6<4096><<<dim3(32, 4), 256, 65536>>>(h1ah, h1al, w2h, w2l, b2, h2);
    final_kernel<<<512, 256>>>(h2, w3, b3, out);
}